// round 1
// baseline (speedup 1.0000x reference)
#include <cuda_runtime.h>
#include <cuda_bf16.h>

#define L 45
#define LP 48            // padded label count (float4-friendly)
#define SMAX 512
#define START_IDX 43
#define STOP_IDX 44

// One block per batch element. threadIdx.x = label row i (0..44 active).
// Per step: alpha[i] = logit[t,i] + mu + log( sum_j expT[i,j] * exp(alpha[j]-mu) )
// where mu is a stale broadcast proxy (alpha of label 0, one step behind) --
// safe because the cross-label spread of alpha is bounded (~16) and the
// per-step drift is small, so exponents stay << fp32 overflow.
__global__ __launch_bounds__(64) void crf_fwd_kernel(
    const float* __restrict__ logits,      // [B, S, L]
    const int*   __restrict__ lens,        // [B]
    const float* __restrict__ trans,       // [L, L], trans[i*L+j] = score(j->i)
    float*       __restrict__ out)         // [B]
{
    const int b = blockIdx.x;
    const int i = threadIdx.x;
    const bool act = (i < L);

    __shared__ float e_s[2][LP];   // double-buffered exp(alpha - mu)
    __shared__ float m_s[2];       // double-buffered proxy scaling
    __shared__ float red[64];      // epilogue reduction

    // zero pad lanes of e buffers once (indices 45..47 stay 0 forever)
    if (i < LP) { e_s[0][i] = 0.f; e_s[1][i] = 0.f; }

    // Each thread holds its expT row in registers.
    float row[LP];
#pragma unroll
    for (int j = 0; j < LP; j++) row[j] = 0.f;
    if (act) {
#pragma unroll
        for (int j = 0; j < L; j++) row[j] = __expf(trans[i * L + j]);
    }

    const int len = lens[b];
    const float* lg = logits + (size_t)b * SMAX * L;

    // ---- step t = 0 analytically: alpha0 = logit[0] + T[:, START] ----
    // (reference's -10000 init makes all other j-contributions exp()->0 in fp32)
    float alpha = 0.f;
    if (act) alpha = lg[i] + trans[i * L + START_IDX];

    if (i == 0) { m_s[0] = alpha; m_s[1] = alpha; }
    __syncthreads();

    float mu = m_s[0];                          // scaling used to build e_s[1]
    if (act) e_s[1][i] = __expf(alpha - mu);

    // ---- main sequential loop: one __syncthreads per step ----
    for (int t = 1; t < len; t++) {
        const int p = t & 1;
        __syncthreads();   // e_s[p] + m_s[p^1] (written last iter) now visible

        // issue the logit load early; consumed ~100+ cycles later
        const float lgt = act ? lg[t * L + i] : 0.f;

        const float4* e4 = (const float4*)(e_s[p]);
        float a0 = 0.f, a1 = 0.f, a2 = 0.f, a3 = 0.f;
#pragma unroll
        for (int q = 0; q < LP / 4; q++) {
            const float4 v = e4[q];             // broadcast read (whole block = same batch)
            a0 = fmaf(row[4 * q + 0], v.x, a0);
            a1 = fmaf(row[4 * q + 1], v.y, a1);
            a2 = fmaf(row[4 * q + 2], v.z, a2);
            a3 = fmaf(row[4 * q + 3], v.w, a3);
        }
        const float s = (a0 + a1) + (a2 + a3);
        alpha = lgt + mu + __logf(s);

        // prepare next iteration (buffer p^1), race-free by parity:
        // readers this iter touch m_s[p^1]; writer targets m_s[p].
        const float mu_next = m_s[p ^ 1];       // alpha_{t-1}[0]
        if (i == 0) m_s[p] = alpha;
        if (act) e_s[p ^ 1][i] = __expf(alpha - mu_next);
        mu = mu_next;
    }

    // ---- epilogue: out[b] = LSE_i( alpha[i] + T[STOP, i] ) ----
    red[i] = act ? (alpha + trans[STOP_IDX * L + i]) : -1e30f;
    __syncthreads();
    if (i == 0) {
        float m = red[0];
#pragma unroll
        for (int j = 1; j < L; j++) m = fmaxf(m, red[j]);
        float s = 0.f;
#pragma unroll
        for (int j = 0; j < L; j++) s += __expf(red[j] - m);
        out[b] = m + __logf(s);
    }
}

extern "C" void kernel_launch(void* const* d_in, const int* in_sizes, int n_in,
                              void* d_out, int out_size) {
    const float* logits = (const float*)d_in[0];   // [1024, 512, 45] f32
    const int*   lens   = (const int*)d_in[1];     // [1024] i32
    const float* trans  = (const float*)d_in[2];   // [45, 45] f32
    float* out = (float*)d_out;                    // [1024] f32

    const int B = in_sizes[1];                     // 1024
    crf_fwd_kernel<<<B, 64>>>(logits, lens, trans, out);
}

// round 2
// speedup vs baseline: 1.1242x; 1.1242x over previous
#include <cuda_runtime.h>
#include <cuda_bf16.h>

#define L 45
#define LP 48            // padded label count (float4-friendly)
#define SMAX 512
#define START_IDX 43
#define STOP_IDX 44
#define PF 4             // logit prefetch distance (covers ~577cyc DRAM latency)

// One block per batch element, threadIdx.x = label row i (0..44 active).
// Running-scale recurrence: e_t[i] = exp(alpha_t[i] - M_t), M scalar per block.
//   s_i      = sum_j expT[i,j] * e[j]
//   e_new[i] = s_i * exp(lgt_i - c)          (M' = M + c)
//   alpha_end[i] = M_end + log(e_end[i])
// c is a stale broadcast proxy (label 0's increment, one step behind) -> off the
// critical path. No per-thread log in the loop; one exp per thread per step.
__global__ __launch_bounds__(64) void crf_fwd_kernel(
    const float* __restrict__ logits,      // [B, S, L]
    const int*   __restrict__ lens,        // [B]
    const float* __restrict__ trans,       // [L, L], trans[i*L+j] = score(j->i)
    float*       __restrict__ out)         // [B]
{
    const int b = blockIdx.x;
    const int i = threadIdx.x;
    const bool act = (i < L);

    __shared__ __align__(16) float e_s[2][LP];  // double-buffered scaled alphas
    __shared__ float c_s[2];                    // double-buffered scale increment
    __shared__ float m_s;                       // initial scale broadcast
    __shared__ float red[64];                   // epilogue reduction

    if (i < LP) { e_s[0][i] = 0.f; e_s[1][i] = 0.f; }
    if (i == 0) { c_s[0] = 0.f; c_s[1] = 0.f; }

    // expT row in registers
    float row[LP];
#pragma unroll
    for (int j = 0; j < LP; j++) row[j] = 0.f;
    if (act) {
#pragma unroll
        for (int j = 0; j < L; j++) row[j] = __expf(trans[i * L + j]);
    }

    const int len = lens[b];
    const float* lg = logits + (size_t)b * SMAX * L;

    // ---- t = 0 analytically: alpha0 = logit[0] + T[:, START] ----
    float alpha0 = 0.f;
    if (act) alpha0 = lg[i] + trans[i * L + START_IDX];
    if (i == 0) m_s = alpha0;
    __syncthreads();

    const float mu0 = m_s;
    float Mloc = mu0;                 // running scale (same value on all threads)
    float e_loc = __expf(alpha0 - mu0);
    if (act) e_s[1][i] = e_loc;       // e_1, scale M = alpha0[0]

    // ---- prefetch logits for steps 1..PF ----
    float lgbuf[PF];
#pragma unroll
    for (int k = 0; k < PF; k++) {
        const int t = 1 + k;
        lgbuf[k] = (act && t < len) ? lg[t * L + i] : 0.f;
    }

    // ---- main loop: 1 barrier / step, no DRAM on critical path ----
    for (int t = 1; t < len; t += PF) {
#pragma unroll
        for (int u = 0; u < PF; u++) {
            const int tt = t + u;
            if (tt < len) {
                const int p = tt & 1;
                __syncthreads();                  // e_s[p], c_s[p^1] visible

                // issue next prefetch early
                const float lgt = lgbuf[u];
                const int tn = tt + PF;
                lgbuf[u] = (act && tn < len) ? lg[tn * L + i] : 0.f;

                const float c = c_s[p ^ 1];
                const float4* e4 = (const float4*)(e_s[p]);
                float a0=0.f,a1=0.f,a2=0.f,a3=0.f,a4=0.f,a5=0.f,a6=0.f,a7=0.f;
#pragma unroll
                for (int q = 0; q < LP / 8; q++) {
                    const float4 va = e4[2 * q];
                    const float4 vb = e4[2 * q + 1];
                    a0 = fmaf(row[8*q+0], va.x, a0);
                    a1 = fmaf(row[8*q+1], va.y, a1);
                    a2 = fmaf(row[8*q+2], va.z, a2);
                    a3 = fmaf(row[8*q+3], va.w, a3);
                    a4 = fmaf(row[8*q+4], vb.x, a4);
                    a5 = fmaf(row[8*q+5], vb.y, a5);
                    a6 = fmaf(row[8*q+6], vb.z, a6);
                    a7 = fmaf(row[8*q+7], vb.w, a7);
                }
                const float s = ((a0+a1)+(a2+a3)) + ((a4+a5)+(a6+a7));

                // e_new = s * exp(lgt - c); scale M' = M + c
                const float en = s * __expf(lgt - c);
                if (act) { e_s[p ^ 1][i] = en; e_loc = en; }
                Mloc += c;

                // thread 0: next step's scale increment (stale proxy, off-path)
                if (i == 0) c_s[p] = __logf(s) + lgt - c;
            }
        }
    }

    // ---- epilogue: out[b] = LSE_i( M + log(e_i) + T[STOP, i] ) ----
    red[i] = act ? (Mloc + __logf(e_loc) + trans[STOP_IDX * L + i]) : -1e30f;
    __syncthreads();
    if (i == 0) {
        float m = red[0];
#pragma unroll
        for (int j = 1; j < L; j++) m = fmaxf(m, red[j]);
        float s = 0.f;
#pragma unroll
        for (int j = 0; j < L; j++) s += __expf(red[j] - m);
        out[b] = m + __logf(s);
    }
}

extern "C" void kernel_launch(void* const* d_in, const int* in_sizes, int n_in,
                              void* d_out, int out_size) {
    const float* logits = (const float*)d_in[0];   // [1024, 512, 45] f32
    const int*   lens   = (const int*)d_in[1];     // [1024] i32
    const float* trans  = (const float*)d_in[2];   // [45, 45] f32
    float* out = (float*)d_out;                    // [1024] f32

    const int B = in_sizes[1];                     // 1024
    crf_fwd_kernel<<<B, 64>>>(logits, lens, trans, out);
}

// round 3
// speedup vs baseline: 1.4360x; 1.2774x over previous
#include <cuda_runtime.h>
#include <cuda_bf16.h>

#define L 45
#define LP 48              // padded label count
#define NPAIR (LP / 2)     // 24 packed f32x2 pairs
#define SMAX 512
#define START_IDX 43
#define STOP_IDX 44
#define PF 4               // logit prefetch distance
#define LOG2E 1.4426950408889634f
#define LN2   0.6931471805599453f

__device__ __forceinline__ float ex2f(float x) {
    float r; asm("ex2.approx.ftz.f32 %0, %1;" : "=f"(r) : "f"(x)); return r;
}
__device__ __forceinline__ float lg2f(float x) {
    float r; asm("lg2.approx.ftz.f32 %0, %1;" : "=f"(r) : "f"(x)); return r;
}
__device__ __forceinline__ void fma2(unsigned long long& d,
                                     unsigned long long a, unsigned long long b) {
    asm("fma.rn.f32x2 %0, %1, %2, %0;" : "+l"(d) : "l"(a), "l"(b));
}
__device__ __forceinline__ void add2(unsigned long long& d, unsigned long long a) {
    asm("add.rn.f32x2 %0, %0, %1;" : "+l"(d) : "l"(a));
}
__device__ __forceinline__ unsigned long long pack2(float lo, float hi) {
    unsigned long long v;
    asm("mov.b64 %0, {%1, %2};" : "=l"(v) : "f"(lo), "f"(hi)); return v;
}
__device__ __forceinline__ float2 unpack2(unsigned long long v) {
    float2 f; asm("mov.b64 {%0, %1}, %2;" : "=f"(f.x), "=f"(f.y) : "l"(v)); return f;
}

// One block per batch. Threads 0..44: e-producers (one label row each, in
// base-2 scaled-linear domain). Thread 45: dedicated scale-increment producer
// (owns a copy of row 0) so the log chain runs in parallel with the exp chain.
// Recurrence (all log-quantities in base 2):
//   s_i  = sum_j expT[i,j] * e[j]          (packed f32x2 dot, row in regs)
//   e'_i = s_i * 2^(lgt2_i - c2)           (M2 += c2)
//   c2'  = lg2(s_0) + lgt2_0 - c2          (stale-by-one proxy, off-path)
__global__ __launch_bounds__(64) void crf_fwd_kernel(
    const float* __restrict__ logits,      // [B, S, L]
    const int*   __restrict__ lens,        // [B]
    const float* __restrict__ trans,       // [L, L], trans[i*L+j]=score(j->i)
    float*       __restrict__ out)         // [B]
{
    const int b = blockIdx.x;
    const int i = threadIdx.x;
    const bool is_e = (i < L);
    const bool is_c = (i == L);            // thread 45
    const bool ld   = is_e | is_c;
    const int  lab  = is_e ? i : 0;        // label row this thread owns

    __shared__ __align__(16) float e_s[2][LP];
    __shared__ float c_s[2];
    __shared__ float m_s;
    __shared__ float red[64];

    if (i < LP) { e_s[0][i] = 0.f; e_s[1][i] = 0.f; }
    if (i == 0) { c_s[0] = 0.f; c_s[1] = 0.f; }

    // packed expT row in registers
    unsigned long long rowp[NPAIR];
#pragma unroll
    for (int m = 0; m < NPAIR; m++) rowp[m] = 0ull;
    if (ld) {
#pragma unroll
        for (int m = 0; m < NPAIR; m++) {
            const float x0 = (2 * m     < L) ? __expf(trans[lab * L + 2 * m])     : 0.f;
            const float x1 = (2 * m + 1 < L) ? __expf(trans[lab * L + 2 * m + 1]) : 0.f;
            rowp[m] = pack2(x0, x1);
        }
    }

    const int len = lens[b];
    const float* lg = logits + (size_t)b * SMAX * L;

    // t = 0 analytically: alpha0 = logit[0] + T[:, START]
    float a0v = 0.f;
    if (is_e) a0v = lg[i] + trans[i * L + START_IDX];
    if (i == 0) m_s = a0v;
    __syncthreads();
    const float mu0 = m_s;
    float M2 = mu0 * LOG2E;                      // running scale (base-2)
    float e_loc = ex2f((a0v - mu0) * LOG2E);
    if (is_e) e_s[1][i] = e_loc;

    // prefetch logits (pre-scaled by log2e, off the critical path)
    float lgbuf[PF];
#pragma unroll
    for (int k = 0; k < PF; k++) {
        const int t = 1 + k;
        lgbuf[k] = (ld && t < len) ? lg[t * L + lab] * LOG2E : 0.f;
    }

#define STEP(tt, uu) do {                                                     \
        const int p_ = (tt) & 1;                                              \
        __syncthreads();                                                      \
        const float lgt2_ = lgbuf[uu];                                        \
        { const int tn_ = (tt) + PF;                                          \
          lgbuf[uu] = (ld && tn_ < len) ? lg[tn_ * L + lab] * LOG2E : 0.f; }  \
        const float c2_ = c_s[p_ ^ 1];                                        \
        const ulonglong2* e2_ = (const ulonglong2*)(e_s[p_]);                 \
        unsigned long long ac_[8] = {0,0,0,0,0,0,0,0};                        \
        _Pragma("unroll")                                                     \
        for (int h_ = 0; h_ < NPAIR / 2; h_++) {                              \
            const ulonglong2 w_ = e2_[h_];                                    \
            fma2(ac_[(2 * h_)     & 7], rowp[2 * h_],     w_.x);              \
            fma2(ac_[(2 * h_ + 1) & 7], rowp[2 * h_ + 1], w_.y);              \
        }                                                                     \
        add2(ac_[0], ac_[4]); add2(ac_[1], ac_[5]);                           \
        add2(ac_[2], ac_[6]); add2(ac_[3], ac_[7]);                           \
        add2(ac_[0], ac_[2]); add2(ac_[1], ac_[3]);                           \
        add2(ac_[0], ac_[1]);                                                 \
        const float2 f_ = unpack2(ac_[0]);                                    \
        const float s_ = f_.x + f_.y;                                         \
        if (is_e) {                                                           \
            const float en_ = s_ * ex2f(lgt2_ - c2_);                         \
            e_s[p_ ^ 1][i] = en_; e_loc = en_;                                \
        }                                                                     \
        if (is_c) c_s[p_] = lg2f(s_) + lgt2_ - c2_;                           \
        M2 += c2_;                                                            \
    } while (0)

    // main loop: full PF-chunks, branch-free bodies (prefetch is predicated)
    int t = 1;
    for (; t + PF <= len; t += PF) {
        STEP(t + 0, 0);
        STEP(t + 1, 1);
        STEP(t + 2, 2);
        STEP(t + 3, 3);
    }
    // tail (<= PF-1 steps)
    for (; t < len; t++) {
        STEP(t, (t - 1) & (PF - 1));
    }
#undef STEP

    // epilogue: out[b] = LSE_i( alpha_i + T[STOP, i] ),  alpha_i = (M2 + lg2 e_i)·ln2
    red[i] = is_e ? ((M2 + lg2f(e_loc)) * LN2 + trans[STOP_IDX * L + i]) : -1e30f;
    __syncthreads();
    if (i == 0) {
        float m = red[0];
#pragma unroll
        for (int j = 1; j < L; j++) m = fmaxf(m, red[j]);
        float s = 0.f;
#pragma unroll
        for (int j = 0; j < L; j++) s += __expf(red[j] - m);
        out[b] = m + __logf(s);
    }
}

extern "C" void kernel_launch(void* const* d_in, const int* in_sizes, int n_in,
                              void* d_out, int out_size) {
    const float* logits = (const float*)d_in[0];   // [1024, 512, 45] f32
    const int*   lens   = (const int*)d_in[1];     // [1024] i32
    const float* trans  = (const float*)d_in[2];   // [45, 45] f32
    float* out = (float*)d_out;                    // [1024] f32

    const int B = in_sizes[1];                     // 1024
    crf_fwd_kernel<<<B, 64>>>(logits, lens, trans, out);
}